// round 12
// baseline (speedup 1.0000x reference)
#include <cuda_runtime.h>
#include <cuda_bf16.h>
#include <cuda_fp16.h>
#include <math.h>
#include <stdint.h>

#define N_NODES 100000
#define N_EDGES 1600000
#define D 128
#define BN_EPS 1e-5f
#define NB_CSR 592
#define CSR_THREADS 256
#define CHUNK ((N_NODES + NB_CSR - 1) / NB_CSR)   // 169

// ---------------- scratch (allocation-free: __device__ globals) ----------------
__device__ __align__(16) __half g_y[(size_t)N_NODES * D];     // x @ W1l (fp16)
__device__ __align__(16) __half g_z[(size_t)N_NODES * D];     // x @ W1r (fp16)
__device__ __align__(16) __half g_hpre[(size_t)N_NODES * D];  // pre-BN h1 (fp16)
__device__ float  g_inv [N_NODES];               // 1/max(deg,1)
__device__ float  g_p   [N_NODES * 2];           // h1 @ W2l
__device__ float  g_r   [N_NODES * 2];           // h1 @ W2r
__device__ float  g_opre[N_NODES * 2];           // pre-BN layer-2 output
__device__ double g_s1[D], g_q1[D];              // BN1 col sum / sumsq
__device__ double g_s2[2], g_q2[2];              // BN2 col sum / sumsq
__device__ float  g_scale1[D], g_shift1[D];      // folded BN1 affine
__device__ int    g_is64;                        // edge_index dtype flag
__device__ int    g_nblk;                        // stats1 completion counter
__device__ int    g_barc;                        // grid-barrier arrival counter
__device__ int    g_barp;                        // grid-barrier phase
// transposed + bf16-split weights: [n=256][k=128], n = [W1l cols | W1r cols]
__device__ __align__(16) __nv_bfloat16 g_wt_h[256 * 128];
__device__ __align__(16) __nv_bfloat16 g_wt_l[256 * 128];
// CSR build
__device__ int    g_cnt[N_NODES];
__device__ int    g_rowstart[N_NODES + 1];
__device__ int    g_cur[N_NODES];
__device__ int    g_partial[NB_CSR];
__device__ int    g_csr[N_EDGES];

// ---------------- helpers ----------------
__device__ __forceinline__ uint32_t smem_u32(const void* p) {
    uint32_t a;
    asm("{ .reg .u64 t; cvta.to.shared.u64 t, %1; cvt.u32.u64 %0, t; }" : "=r"(a) : "l"(p));
    return a;
}
__device__ __forceinline__ void bf16_split2(float x0, float x1, uint32_t& hi, uint32_t& lo) {
    __nv_bfloat16 h0 = __float2bfloat16(x0), h1 = __float2bfloat16(x1);
    __nv_bfloat162 hp = __halves2bfloat162(h0, h1);
    __nv_bfloat162 lp = __halves2bfloat162(
        __float2bfloat16(x0 - __bfloat162float(h0)),
        __float2bfloat16(x1 - __bfloat162float(h1)));
    hi = *(uint32_t*)&hp;
    lo = *(uint32_t*)&lp;
}
#define LDSM4(r, addr) \
    asm volatile("ldmatrix.sync.aligned.m8n8.x4.shared.b16 {%0,%1,%2,%3}, [%4];" \
        : "=r"((r)[0]), "=r"((r)[1]), "=r"((r)[2]), "=r"((r)[3]) : "r"(addr))
#define MMA16816(c, a, b0, b1) \
    asm volatile("mma.sync.aligned.m16n8k16.row.col.f32.bf16.bf16.f32 " \
        "{%0,%1,%2,%3}, {%4,%5,%6,%7}, {%8,%9}, {%0,%1,%2,%3};" \
        : "+f"((c)[0]), "+f"((c)[1]), "+f"((c)[2]), "+f"((c)[3]) \
        : "r"((a)[0]), "r"((a)[1]), "r"((a)[2]), "r"((a)[3]), "r"(b0), "r"(b1))

// ---------------- prep: dtype detect + zero scratch + W split ----------------
__global__ void k_prep(const int* __restrict__ ei,
                       const float* __restrict__ W1l, const float* __restrict__ W1r) {
    int i = blockIdx.x * blockDim.x + threadIdx.x;
    int stride = gridDim.x * blockDim.x;
    if (blockIdx.x == 0) {
        __shared__ int any_nonzero;
        if (threadIdx.x == 0) any_nonzero = 0;
        __syncthreads();
        int v = ei[2 * threadIdx.x + 1];
        if (v != 0) atomicOr(&any_nonzero, 1);
        __syncthreads();
        if (threadIdx.x == 0) {
            g_is64 = (any_nonzero == 0) ? 1 : 0;
            g_nblk = 0;
            g_barc = 0;
            g_barp = 0;
        }
    }
    for (int j = i; j < N_NODES; j += stride) g_cnt[j] = 0;
    if (i < D) { g_s1[i] = 0.0; g_q1[i] = 0.0; }
    if (i < 2) { g_s2[i] = 0.0; g_q2[i] = 0.0; }
    for (int j = i; j < 256 * 128; j += stride) {
        int n = j >> 7, k = j & 127;
        float w = (n < 128) ? __ldg(W1l + k * 128 + n) : __ldg(W1r + k * 128 + (n - 128));
        __nv_bfloat16 h = __float2bfloat16(w);
        g_wt_h[j] = h;                               // j == n*128 + k
        g_wt_l[j] = __float2bfloat16(w - __bfloat162float(h));
    }
}

// ---------------- fused CSR build: hist -> scan -> scatter (one kernel) ------
// 592 blocks (4/SM alone) are guaranteed co-resident -> spin grid barrier safe.
__device__ __forceinline__ void grid_bar(int phase) {
    __syncthreads();
    if (threadIdx.x == 0) {
        __threadfence();
        int t = atomicAdd(&g_barc, 1);
        if (t == NB_CSR * phase - 1) {
            atomicExch(&g_barp, phase);
        } else {
            while (atomicAdd(&g_barp, 0) < phase) __nanosleep(64);
        }
        __threadfence();
    }
    __syncthreads();
}

__global__ void __launch_bounds__(CSR_THREADS) k_csr(const int* __restrict__ ei) {
    __shared__ int sh[CSR_THREADS];
    const int b = blockIdx.x, tid = threadIdx.x;
    const int gsz = NB_CSR * CSR_THREADS;
    const int is64 = g_is64;

    // phase A: histogram of dst
    for (int t = b * CSR_THREADS + tid; t < N_EDGES / 2; t += gsz) {
        int d0, d1;
        if (is64) {
            longlong2 v = __ldg((const longlong2*)((const long long*)ei + N_EDGES) + t);
            d0 = (int)v.x; d1 = (int)v.y;
        } else {
            int2 v = __ldg((const int2*)(ei + N_EDGES) + t);
            d0 = v.x; d1 = v.y;
        }
        atomicAdd(&g_cnt[d0], 1);
        atomicAdd(&g_cnt[d1], 1);
    }
    grid_bar(1);

    // phase B: per-block partial total over its CHUNK of nodes
    const int i0 = b * CHUNK;
    int v = 0;
    if (tid < CHUNK && i0 + tid < N_NODES) v = g_cnt[i0 + tid];
    sh[tid] = v;
    __syncthreads();
    #pragma unroll
    for (int off = 128; off; off >>= 1) {
        if (tid < off) sh[tid] += sh[tid + off];
        __syncthreads();
    }
    if (tid == 0) g_partial[b] = sh[0];
    grid_bar(2);

    // phase C: prefix of partials + local exclusive scan
    int pre = 0;
    for (int j = tid; j < b; j += CSR_THREADS) pre += g_partial[j];
    sh[tid] = pre;
    __syncthreads();
    #pragma unroll
    for (int off = 128; off; off >>= 1) {
        if (tid < off) sh[tid] += sh[tid + off];
        __syncthreads();
    }
    const int block_pre = sh[0];
    __syncthreads();
    sh[tid] = v;
    __syncthreads();
    #pragma unroll
    for (int off = 1; off < CSR_THREADS; off <<= 1) {
        int t2 = (tid >= off) ? sh[tid - off] : 0;
        __syncthreads();
        sh[tid] += t2;
        __syncthreads();
    }
    if (tid < CHUNK && i0 + tid < N_NODES) {
        int rs = block_pre + sh[tid] - v;   // exclusive scan value
        g_rowstart[i0 + tid] = rs;
        g_cur[i0 + tid] = rs;
    }
    if (b == 0 && tid == 0) g_rowstart[N_NODES] = N_EDGES;
    grid_bar(3);

    // phase D: scatter src ids into CSR slots
    for (int t = b * CSR_THREADS + tid; t < N_EDGES / 2; t += gsz) {
        int s0, d0, s1, d1;
        if (is64) {
            const long long* E = (const long long*)ei;
            longlong2 sv = __ldg((const longlong2*)E + t);
            longlong2 dv = __ldg((const longlong2*)(E + N_EDGES) + t);
            s0 = (int)sv.x; s1 = (int)sv.y; d0 = (int)dv.x; d1 = (int)dv.y;
        } else {
            int2 sv = __ldg((const int2*)ei + t);
            int2 dv = __ldg((const int2*)(ei + N_EDGES) + t);
            s0 = sv.x; s1 = sv.y; d0 = dv.x; d1 = dv.y;
        }
        g_csr[atomicAdd(&g_cur[d0], 1)] = s0;
        g_csr[atomicAdd(&g_cur[d1], 1)] = s1;
    }
}

// ---------------- layer-1 GEMM: [y|z] = x @ [W1l|W1r] (HMMA split-bf16) ------
#define BK 32
#define LDA 40   // smem row stride in bf16 (32 + 8 pad)

__global__ void __launch_bounds__(256, 2) k_gemm1(const float* __restrict__ x) {
    __shared__ __align__(16) __nv_bfloat16 As_h[128 * LDA];
    __shared__ __align__(16) __nv_bfloat16 As_l[128 * LDA];
    __shared__ __align__(16) __nv_bfloat16 Bs_h[128 * LDA];
    __shared__ __align__(16) __nv_bfloat16 Bs_l[128 * LDA];

    const int tid = threadIdx.x;
    const int wid = tid >> 5, l = tid & 31;
    const int warp_m = wid >> 2, warp_n = wid & 3;
    const int m0 = blockIdx.x * 128;
    const int nh = blockIdx.y;

    const uint32_t sAh = smem_u32(As_h), sAl = smem_u32(As_l);
    const uint32_t sBh = smem_u32(Bs_h), sBl = smem_u32(Bs_l);

    float acc[4][4][4];
    #pragma unroll
    for (int i = 0; i < 4; i++)
        #pragma unroll
        for (int j = 0; j < 4; j++)
            #pragma unroll
            for (int c = 0; c < 4; c++) acc[i][j][c] = 0.f;

    const int st_r  = tid >> 1;          // 0..127
    const int st_kh = (tid & 1) * 16;    // 0 / 16
    const int m_st  = m0 + st_r;

    float4 f[4];
    uint4  bh[2], bl[2];

    auto loadT = [&](int kc) {
        if (m_st < N_NODES) {
            const float4* rp = (const float4*)(x + (size_t)m_st * D + kc + st_kh);
            f[0] = __ldg(rp); f[1] = __ldg(rp + 1); f[2] = __ldg(rp + 2); f[3] = __ldg(rp + 3);
        } else {
            f[0] = f[1] = f[2] = f[3] = make_float4(0.f, 0.f, 0.f, 0.f);
        }
        const uint4* ph = (const uint4*)(g_wt_h + (size_t)(nh * 128 + st_r) * 128 + kc + st_kh);
        const uint4* pl = (const uint4*)(g_wt_l + (size_t)(nh * 128 + st_r) * 128 + kc + st_kh);
        bh[0] = __ldg(ph); bh[1] = __ldg(ph + 1);
        bl[0] = __ldg(pl); bl[1] = __ldg(pl + 1);
    };
    auto storeT = [&]() {
        uint32_t* dh = (uint32_t*)(As_h + st_r * LDA + st_kh);
        uint32_t* dl = (uint32_t*)(As_l + st_r * LDA + st_kh);
        #pragma unroll
        for (int q = 0; q < 4; q++) {
            uint32_t h0, l0, h1, l1;
            bf16_split2(f[q].x, f[q].y, h0, l0);
            bf16_split2(f[q].z, f[q].w, h1, l1);
            dh[q * 2] = h0; dh[q * 2 + 1] = h1;
            dl[q * 2] = l0; dl[q * 2 + 1] = l1;
        }
        uint4* bdh = (uint4*)(Bs_h + st_r * LDA + st_kh);
        uint4* bdl = (uint4*)(Bs_l + st_r * LDA + st_kh);
        bdh[0] = bh[0]; bdh[1] = bh[1];
        bdl[0] = bl[0]; bdl[1] = bl[1];
    };

    loadT(0);

    for (int kt = 0; kt < 4; kt++) {
        if (kt) __syncthreads();
        storeT();
        __syncthreads();
        if (kt < 3) loadT((kt + 1) * BK);     // LDGs in flight during compute
        #pragma unroll
        for (int kk = 0; kk < 2; kk++) {
            uint32_t ah[4][4], al[4][4], bhf[2][4], blf[2][4];
            #pragma unroll
            for (int mt = 0; mt < 4; mt++) {
                uint32_t off = (uint32_t)(((warp_m * 64 + mt * 16 + (l & 15)) * LDA
                                           + kk * 16 + (l >> 4) * 8) * 2);
                LDSM4(ah[mt], sAh + off);
                LDSM4(al[mt], sAl + off);
            }
            #pragma unroll
            for (int p = 0; p < 2; p++) {
                uint32_t off = (uint32_t)(((warp_n * 32 + p * 16 + (l >> 4) * 8 + (l & 7)) * LDA
                                           + kk * 16 + ((l >> 3) & 1) * 8) * 2);
                LDSM4(bhf[p], sBh + off);
                LDSM4(blf[p], sBl + off);
            }
            #pragma unroll
            for (int mt = 0; mt < 4; mt++)
                #pragma unroll
                for (int nt = 0; nt < 4; nt++) {
                    const int p = nt >> 1, q = nt & 1;
                    MMA16816(acc[mt][nt], ah[mt], bhf[p][2 * q], bhf[p][2 * q + 1]);
                    MMA16816(acc[mt][nt], ah[mt], blf[p][2 * q], blf[p][2 * q + 1]);
                    MMA16816(acc[mt][nt], al[mt], bhf[p][2 * q], bhf[p][2 * q + 1]);
                }
        }
    }

    // ---- epilogue: store fp16 y/z ----
    __half* dst = nh ? g_z : g_y;
    #pragma unroll
    for (int mt = 0; mt < 4; mt++) {
        #pragma unroll
        for (int hh = 0; hh < 2; hh++) {
            int m = m0 + warp_m * 64 + mt * 16 + hh * 8 + (l >> 2);
            if (m < N_NODES) {
                #pragma unroll
                for (int nt = 0; nt < 4; nt++) {
                    int n = warp_n * 32 + nt * 8 + (l & 3) * 2;
                    __half2 hv = __floats2half2_rn(acc[mt][nt][hh * 2 + 0],
                                                   acc[mt][nt][hh * 2 + 1]);
                    *(__half2*)(dst + (size_t)m * D + n) = hv;
                }
            }
        }
    }
}

// ------ fused: mean-agg(y) + z + b1 -> hpre (fp16); one node per warp --------
__global__ void __launch_bounds__(256) k_aggfuse(const float* __restrict__ b1) {
    int gi = blockIdx.x * blockDim.x + threadIdx.x;
    int n = gi >> 5;
    int l = gi & 31;
    if (n >= N_NODES) return;
    int beg = g_rowstart[n], end = g_rowstart[n + 1];
    float4 a0 = make_float4(0.f, 0.f, 0.f, 0.f);
    float4 a1 = make_float4(0.f, 0.f, 0.f, 0.f);
    for (int base = beg; base < end; base += 32) {
        int cnt = min(32, end - base);
        int sid = (base + l < end) ? __ldg(g_csr + base + l) : 0;
        int j = 0;
        for (; j + 1 < cnt; j += 2) {
            int s0 = __shfl_sync(0xffffffffu, sid, j);
            int s1 = __shfl_sync(0xffffffffu, sid, j + 1);
            uint2 v0 = __ldg((const uint2*)(g_y + (size_t)s0 * D) + l);
            uint2 v1 = __ldg((const uint2*)(g_y + (size_t)s1 * D) + l);
            float2 p = __half22float2(*(__half2*)&v0.x);
            float2 r = __half22float2(*(__half2*)&v0.y);
            a0.x += p.x; a0.y += p.y; a0.z += r.x; a0.w += r.y;
            p = __half22float2(*(__half2*)&v1.x);
            r = __half22float2(*(__half2*)&v1.y);
            a1.x += p.x; a1.y += p.y; a1.z += r.x; a1.w += r.y;
        }
        if (j < cnt) {
            int s0 = __shfl_sync(0xffffffffu, sid, j);
            uint2 v0 = __ldg((const uint2*)(g_y + (size_t)s0 * D) + l);
            float2 p = __half22float2(*(__half2*)&v0.x);
            float2 r = __half22float2(*(__half2*)&v0.y);
            a0.x += p.x; a0.y += p.y; a0.z += r.x; a0.w += r.y;
        }
    }
    float inv = 1.0f / fmaxf((float)(end - beg), 1.0f);
    float4 bb = __ldg((const float4*)b1 + l);
    uint2 zv = __ldg((const uint2*)(g_z + (size_t)n * D) + l);
    float2 z0 = __half22float2(*(__half2*)&zv.x);
    float2 z1 = __half22float2(*(__half2*)&zv.y);
    float v0 = fmaf(a0.x + a1.x, inv, z0.x + bb.x);
    float v1 = fmaf(a0.y + a1.y, inv, z0.y + bb.y);
    float v2 = fmaf(a0.z + a1.z, inv, z1.x + bb.z);
    float v3 = fmaf(a0.w + a1.w, inv, z1.y + bb.w);
    __half2 h0 = __floats2half2_rn(v0, v1);
    __half2 h1 = __floats2half2_rn(v2, v3);
    *(uint2*)(g_hpre + (size_t)n * D + l * 4) =
        make_uint2(*(uint32_t*)&h0, *(uint32_t*)&h1);
    if (l == 0) g_inv[n] = inv;
}

// ------- BN1 stats + fold (last block computes params) -----------------------
__global__ void k_stats1(const float* __restrict__ gamma1,
                         const float* __restrict__ beta1) {
    int c = threadIdx.x;            // 128 threads, one column each
    float s = 0.f, q = 0.f;
    for (int r = blockIdx.x; r < N_NODES; r += gridDim.x) {
        float v = __half2float(g_hpre[(size_t)r * D + c]);
        s += v; q += v * v;
    }
    atomicAdd(&g_s1[c], (double)s);
    atomicAdd(&g_q1[c], (double)q);
    __threadfence();
    __shared__ int last;
    __syncthreads();
    if (c == 0) last = (atomicAdd(&g_nblk, 1) == gridDim.x - 1) ? 1 : 0;
    __syncthreads();
    if (last) {
        double mu  = g_s1[c] / (double)N_NODES;
        double var = g_q1[c] / (double)N_NODES - mu * mu;
        double sc  = (double)gamma1[c] / sqrt(var + (double)BN_EPS);
        g_scale1[c] = (float)sc;
        g_shift1[c] = (float)((double)beta1[c] - mu * sc);
    }
}

// ---------------- BN1 + ReLU + project to 2 dims (warp per node) -------------
__global__ void k_proj(const float* __restrict__ W2l, const float* __restrict__ W2r) {
    int gi = blockIdx.x * blockDim.x + threadIdx.x;
    int n    = gi >> 5;
    int lane = threadIdx.x & 31;
    if (n >= N_NODES) return;
    uint2 hv2 = __ldg((const uint2*)(g_hpre + (size_t)n * D) + lane);
    float2 fa = __half22float2(*(__half2*)&hv2.x);
    float2 fb = __half22float2(*(__half2*)&hv2.y);
    float hv[4] = {fa.x, fa.y, fb.x, fb.y};
    float p0 = 0.f, p1 = 0.f, r0 = 0.f, r1 = 0.f;
    #pragma unroll
    for (int j = 0; j < 4; j++) {
        int c = lane * 4 + j;
        float v = fmaxf(fmaf(hv[j], g_scale1[c], g_shift1[c]), 0.f);
        p0 = fmaf(v, W2l[2 * c],     p0);
        p1 = fmaf(v, W2l[2 * c + 1], p1);
        r0 = fmaf(v, W2r[2 * c],     r0);
        r1 = fmaf(v, W2r[2 * c + 1], r1);
    }
    #pragma unroll
    for (int o = 16; o; o >>= 1) {
        p0 += __shfl_xor_sync(0xffffffffu, p0, o);
        p1 += __shfl_xor_sync(0xffffffffu, p1, o);
        r0 += __shfl_xor_sync(0xffffffffu, r0, o);
        r1 += __shfl_xor_sync(0xffffffffu, r1, o);
    }
    if (lane == 0) {
        *(float2*)(g_p + 2 * n) = make_float2(p0, p1);
        *(float2*)(g_r + 2 * n) = make_float2(r0, r1);
    }
}

// ---------------- layer 2: CSR gather + outpre + BN2 stats (fused) ----------
__global__ void k_l2(const float* __restrict__ b2) {
    int i = blockIdx.x * blockDim.x + threadIdx.x;
    float o0 = 0.f, o1 = 0.f;
    if (i < N_NODES) {
        int beg = g_rowstart[i], end = g_rowstart[i + 1];
        float s0 = 0.f, s1 = 0.f, t0 = 0.f, t1 = 0.f;
        int e = beg;
        for (; e + 1 < end; e += 2) {
            int sa = __ldg(g_csr + e);
            int sb = __ldg(g_csr + e + 1);
            float2 va = *(const float2*)(g_p + 2 * sa);
            float2 vb = *(const float2*)(g_p + 2 * sb);
            s0 += va.x; s1 += va.y;
            t0 += vb.x; t1 += vb.y;
        }
        if (e < end) {
            int sa = __ldg(g_csr + e);
            float2 va = *(const float2*)(g_p + 2 * sa);
            s0 += va.x; s1 += va.y;
        }
        s0 += t0; s1 += t1;
        float inv = g_inv[i];
        float2 r = *(const float2*)(g_r + 2 * i);
        o0 = fmaf(s0, inv, b2[0] + r.x);
        o1 = fmaf(s1, inv, b2[1] + r.y);
        *(float2*)(g_opre + 2 * i) = make_float2(o0, o1);
    }
    float q0 = o0 * o0, q1 = o1 * o1;
    #pragma unroll
    for (int o = 16; o; o >>= 1) {
        o0 += __shfl_xor_sync(0xffffffffu, o0, o);
        o1 += __shfl_xor_sync(0xffffffffu, o1, o);
        q0 += __shfl_xor_sync(0xffffffffu, q0, o);
        q1 += __shfl_xor_sync(0xffffffffu, q1, o);
    }
    __shared__ float sh[4][8];
    int w = threadIdx.x >> 5, ll = threadIdx.x & 31;
    if (ll == 0) { sh[0][w] = o0; sh[1][w] = o1; sh[2][w] = q0; sh[3][w] = q1; }
    __syncthreads();
    if (threadIdx.x == 0) {
        float s0 = 0.f, s1 = 0.f, t0 = 0.f, t1 = 0.f;
        #pragma unroll
        for (int k = 0; k < 8; k++) { s0 += sh[0][k]; s1 += sh[1][k]; t0 += sh[2][k]; t1 += sh[3][k]; }
        atomicAdd(&g_s2[0], (double)s0);
        atomicAdd(&g_s2[1], (double)s1);
        atomicAdd(&g_q2[0], (double)t0);
        atomicAdd(&g_q2[1], (double)t1);
    }
}

// ---------------- BN2 + log_softmax ----------------
__global__ void k_final(const float* __restrict__ gamma2, const float* __restrict__ beta2,
                        float* __restrict__ out) {
    int i = blockIdx.x * blockDim.x + threadIdx.x;
    if (i >= N_NODES) return;
    double mu0 = g_s2[0] / (double)N_NODES;
    double mu1 = g_s2[1] / (double)N_NODES;
    double v0  = g_q2[0] / (double)N_NODES - mu0 * mu0;
    double v1  = g_q2[1] / (double)N_NODES - mu1 * mu1;
    float sc0 = (float)((double)gamma2[0] / sqrt(v0 + (double)BN_EPS));
    float sc1 = (float)((double)gamma2[1] / sqrt(v1 + (double)BN_EPS));
    float sh0 = (float)((double)beta2[0] - mu0 * sc0);
    float sh1 = (float)((double)beta2[1] - mu1 * sc1);
    float2 o = *(const float2*)(g_opre + 2 * i);
    float a = fmaf(o.x, sc0, sh0);
    float b = fmaf(o.y, sc1, sh1);
    float m = fmaxf(a, b);
    float lse = m + logf(expf(a - m) + expf(b - m));
    *(float2*)(out + 2 * i) = make_float2(a - lse, b - lse);
}

// ---------------- launch: CSR (one kernel, s2) overlaps gemm (main) ----------
extern "C" void kernel_launch(void* const* d_in, const int* in_sizes, int n_in,
                              void* d_out, int out_size) {
    const float* x    = (const float*)d_in[0];
    const int*   ei   = (const int*)d_in[1];
    const float* W1l  = (const float*)d_in[2];
    const float* b1   = (const float*)d_in[3];
    const float* W1r  = (const float*)d_in[4];
    const float* g1   = (const float*)d_in[5];
    const float* be1  = (const float*)d_in[6];
    const float* W2l  = (const float*)d_in[7];
    const float* b2   = (const float*)d_in[8];
    const float* W2r  = (const float*)d_in[9];
    const float* g2   = (const float*)d_in[10];
    const float* be2  = (const float*)d_in[11];
    float* out = (float*)d_out;

    cudaStream_t s2;
    cudaStreamCreateWithFlags(&s2, cudaStreamNonBlocking);
    cudaEvent_t e1, e2;
    cudaEventCreateWithFlags(&e1, cudaEventDisableTiming);
    cudaEventCreateWithFlags(&e2, cudaEventDisableTiming);

    k_prep<<<200, 256>>>(ei, W1l, W1r);                          // launch 1
    cudaEventRecord(e1, 0);
    cudaStreamWaitEvent(s2, e1, 0);                              // fork

    k_csr<<<NB_CSR, CSR_THREADS, 0, s2>>>(ei);                   // launch 2 (s2)
    k_gemm1<<<dim3((N_NODES + 127) / 128, 2), 256>>>(x);         // launch 3 (main)

    cudaEventRecord(e2, s2);
    cudaStreamWaitEvent(0, e2, 0);                               // join

    k_aggfuse<<<(N_NODES * 32 + 255) / 256, 256>>>(b1);          // launch 4 (profiled)
    k_stats1<<<800, 128>>>(g1, be1);
    k_proj<<<(N_NODES * 32 + 255) / 256, 256>>>(W2l, W2r);
    k_l2<<<(N_NODES + 255) / 256, 256>>>(b2);
    k_final<<<(N_NODES + 255) / 256, 256>>>(g2, be2, out);
}

// round 13
// speedup vs baseline: 1.2638x; 1.2638x over previous
#include <cuda_runtime.h>
#include <cuda_bf16.h>
#include <cuda_fp16.h>
#include <math.h>
#include <stdint.h>

#define N_NODES 100000
#define N_EDGES 1600000
#define D 128
#define BN_EPS 1e-5f
#define SCAN_BLK 1024
#define N_SCAN_BLKS ((N_NODES + SCAN_BLK - 1) / SCAN_BLK)   // 98
#define NB_SP 1480            // statsproj blocks (10/SM, co-resident)
#define NB_L2 ((N_NODES + 255) / 256)   // 391 (co-resident)

// ---------------- scratch (allocation-free: __device__ globals) ----------------
__device__ __align__(16) __half g_y[(size_t)N_NODES * D];     // x @ W1l (fp16)
__device__ __align__(16) __half g_z[(size_t)N_NODES * D];     // x @ W1r (fp16)
__device__ __align__(16) __half g_hpre[(size_t)N_NODES * D];  // pre-BN h1 (fp16)
__device__ float  g_inv [N_NODES];               // 1/max(deg,1)
__device__ float  g_p   [N_NODES * 2];           // h1 @ W2l
__device__ float  g_r   [N_NODES * 2];           // h1 @ W2r
__device__ double g_s1[D], g_q1[D];              // BN1 col sum / sumsq
__device__ double g_s2[2], g_q2[2];              // BN2 col sum / sumsq
__device__ int    g_is64;                        // edge_index dtype flag
__device__ int    g_bc1, g_bp1;                  // statsproj grid barrier
__device__ int    g_bc2, g_bp2;                  // l2final grid barrier
// transposed + bf16-split weights: [n=256][k=128], n = [W1l cols | W1r cols]
__device__ __align__(16) __nv_bfloat16 g_wt_h[256 * 128];
__device__ __align__(16) __nv_bfloat16 g_wt_l[256 * 128];
// CSR build
__device__ int    g_cnt[N_NODES];
__device__ int    g_rowtmp[N_NODES];
__device__ int    g_rowstart[N_NODES + 1];
__device__ int    g_cur[N_NODES];
__device__ int    g_partial[N_SCAN_BLKS];
__device__ int    g_csr[N_EDGES];

// ---------------- helpers ----------------
__device__ __forceinline__ uint32_t smem_u32(const void* p) {
    uint32_t a;
    asm("{ .reg .u64 t; cvta.to.shared.u64 t, %1; cvt.u32.u64 %0, t; }" : "=r"(a) : "l"(p));
    return a;
}
__device__ __forceinline__ void bf16_split2(float x0, float x1, uint32_t& hi, uint32_t& lo) {
    __nv_bfloat16 h0 = __float2bfloat16(x0), h1 = __float2bfloat16(x1);
    __nv_bfloat162 hp = __halves2bfloat162(h0, h1);
    __nv_bfloat162 lp = __halves2bfloat162(
        __float2bfloat16(x0 - __bfloat162float(h0)),
        __float2bfloat16(x1 - __bfloat162float(h1)));
    hi = *(uint32_t*)&hp;
    lo = *(uint32_t*)&lp;
}
#define LDSM4(r, addr) \
    asm volatile("ldmatrix.sync.aligned.m8n8.x4.shared.b16 {%0,%1,%2,%3}, [%4];" \
        : "=r"((r)[0]), "=r"((r)[1]), "=r"((r)[2]), "=r"((r)[3]) : "r"(addr))
#define MMA16816(c, a, b0, b1) \
    asm volatile("mma.sync.aligned.m16n8k16.row.col.f32.bf16.bf16.f32 " \
        "{%0,%1,%2,%3}, {%4,%5,%6,%7}, {%8,%9}, {%0,%1,%2,%3};" \
        : "+f"((c)[0]), "+f"((c)[1]), "+f"((c)[2]), "+f"((c)[3]) \
        : "r"((a)[0]), "r"((a)[1]), "r"((a)[2]), "r"((a)[3]), "r"(b0), "r"(b1))

// grid barrier for co-resident grids (kernel runs alone on the GPU)
__device__ __forceinline__ void grid_bar(int* cnt, int* phs, int nblk, int phase) {
    __syncthreads();
    if (threadIdx.x == 0) {
        __threadfence();
        int t = atomicAdd(cnt, 1);
        if (t == nblk * phase - 1) {
            atomicExch(phs, phase);
        } else {
            while (atomicAdd(phs, 0) < phase) __nanosleep(64);
        }
        __threadfence();
    }
    __syncthreads();
}

// ---------------- prep: dtype detect + zero scratch + W split ----------------
__global__ void k_prep(const int* __restrict__ ei,
                       const float* __restrict__ W1l, const float* __restrict__ W1r) {
    int i = blockIdx.x * blockDim.x + threadIdx.x;
    int stride = gridDim.x * blockDim.x;
    if (blockIdx.x == 0) {
        __shared__ int any_nonzero;
        if (threadIdx.x == 0) any_nonzero = 0;
        __syncthreads();
        int v = ei[2 * threadIdx.x + 1];
        if (v != 0) atomicOr(&any_nonzero, 1);
        __syncthreads();
        if (threadIdx.x == 0) {
            g_is64 = (any_nonzero == 0) ? 1 : 0;
            g_bc1 = 0; g_bp1 = 0; g_bc2 = 0; g_bp2 = 0;
        }
    }
    for (int j = i; j < N_NODES; j += stride) g_cnt[j] = 0;
    if (i < D) { g_s1[i] = 0.0; g_q1[i] = 0.0; }
    if (i < 2) { g_s2[i] = 0.0; g_q2[i] = 0.0; }
    for (int j = i; j < 256 * 128; j += stride) {
        int n = j >> 7, k = j & 127;
        float w = (n < 128) ? __ldg(W1l + k * 128 + n) : __ldg(W1r + k * 128 + (n - 128));
        __nv_bfloat16 h = __float2bfloat16(w);
        g_wt_h[j] = h;                               // j == n*128 + k
        g_wt_l[j] = __float2bfloat16(w - __bfloat162float(h));
    }
}

// ---------------- layer-1 GEMM: [y|z] = x @ [W1l|W1r] (HMMA split-bf16) ------
#define BK 32
#define LDA 40   // smem row stride in bf16 (32 + 8 pad)

__global__ void __launch_bounds__(256, 2) k_gemm1(const float* __restrict__ x) {
    __shared__ __align__(16) __nv_bfloat16 As_h[128 * LDA];
    __shared__ __align__(16) __nv_bfloat16 As_l[128 * LDA];
    __shared__ __align__(16) __nv_bfloat16 Bs_h[128 * LDA];
    __shared__ __align__(16) __nv_bfloat16 Bs_l[128 * LDA];

    const int tid = threadIdx.x;
    const int wid = tid >> 5, l = tid & 31;
    const int warp_m = wid >> 2, warp_n = wid & 3;
    const int m0 = blockIdx.x * 128;
    const int nh = blockIdx.y;

    const uint32_t sAh = smem_u32(As_h), sAl = smem_u32(As_l);
    const uint32_t sBh = smem_u32(Bs_h), sBl = smem_u32(Bs_l);

    float acc[4][4][4];
    #pragma unroll
    for (int i = 0; i < 4; i++)
        #pragma unroll
        for (int j = 0; j < 4; j++)
            #pragma unroll
            for (int c = 0; c < 4; c++) acc[i][j][c] = 0.f;

    const int st_r  = tid >> 1;
    const int st_kh = (tid & 1) * 16;
    const int m_st  = m0 + st_r;

    float4 f[4];
    uint4  bh[2], bl[2];

    auto loadT = [&](int kc) {
        if (m_st < N_NODES) {
            const float4* rp = (const float4*)(x + (size_t)m_st * D + kc + st_kh);
            f[0] = __ldg(rp); f[1] = __ldg(rp + 1); f[2] = __ldg(rp + 2); f[3] = __ldg(rp + 3);
        } else {
            f[0] = f[1] = f[2] = f[3] = make_float4(0.f, 0.f, 0.f, 0.f);
        }
        const uint4* ph = (const uint4*)(g_wt_h + (size_t)(nh * 128 + st_r) * 128 + kc + st_kh);
        const uint4* pl = (const uint4*)(g_wt_l + (size_t)(nh * 128 + st_r) * 128 + kc + st_kh);
        bh[0] = __ldg(ph); bh[1] = __ldg(ph + 1);
        bl[0] = __ldg(pl); bl[1] = __ldg(pl + 1);
    };
    auto storeT = [&]() {
        uint32_t* dh = (uint32_t*)(As_h + st_r * LDA + st_kh);
        uint32_t* dl = (uint32_t*)(As_l + st_r * LDA + st_kh);
        #pragma unroll
        for (int q = 0; q < 4; q++) {
            uint32_t h0, l0, h1, l1;
            bf16_split2(f[q].x, f[q].y, h0, l0);
            bf16_split2(f[q].z, f[q].w, h1, l1);
            dh[q * 2] = h0; dh[q * 2 + 1] = h1;
            dl[q * 2] = l0; dl[q * 2 + 1] = l1;
        }
        uint4* bdh = (uint4*)(Bs_h + st_r * LDA + st_kh);
        uint4* bdl = (uint4*)(Bs_l + st_r * LDA + st_kh);
        bdh[0] = bh[0]; bdh[1] = bh[1];
        bdl[0] = bl[0]; bdl[1] = bl[1];
    };

    loadT(0);

    for (int kt = 0; kt < 4; kt++) {
        if (kt) __syncthreads();
        storeT();
        __syncthreads();
        if (kt < 3) loadT((kt + 1) * BK);
        #pragma unroll
        for (int kk = 0; kk < 2; kk++) {
            uint32_t ah[4][4], al[4][4], bhf[2][4], blf[2][4];
            #pragma unroll
            for (int mt = 0; mt < 4; mt++) {
                uint32_t off = (uint32_t)(((warp_m * 64 + mt * 16 + (l & 15)) * LDA
                                           + kk * 16 + (l >> 4) * 8) * 2);
                LDSM4(ah[mt], sAh + off);
                LDSM4(al[mt], sAl + off);
            }
            #pragma unroll
            for (int p = 0; p < 2; p++) {
                uint32_t off = (uint32_t)(((warp_n * 32 + p * 16 + (l >> 4) * 8 + (l & 7)) * LDA
                                           + kk * 16 + ((l >> 3) & 1) * 8) * 2);
                LDSM4(bhf[p], sBh + off);
                LDSM4(blf[p], sBl + off);
            }
            #pragma unroll
            for (int mt = 0; mt < 4; mt++)
                #pragma unroll
                for (int nt = 0; nt < 4; nt++) {
                    const int p = nt >> 1, q = nt & 1;
                    MMA16816(acc[mt][nt], ah[mt], bhf[p][2 * q], bhf[p][2 * q + 1]);
                    MMA16816(acc[mt][nt], ah[mt], blf[p][2 * q], blf[p][2 * q + 1]);
                    MMA16816(acc[mt][nt], al[mt], bhf[p][2 * q], bhf[p][2 * q + 1]);
                }
        }
    }

    __half* dst = nh ? g_z : g_y;
    #pragma unroll
    for (int mt = 0; mt < 4; mt++) {
        #pragma unroll
        for (int hh = 0; hh < 2; hh++) {
            int m = m0 + warp_m * 64 + mt * 16 + hh * 8 + (l >> 2);
            if (m < N_NODES) {
                #pragma unroll
                for (int nt = 0; nt < 4; nt++) {
                    int n = warp_n * 32 + nt * 8 + (l & 3) * 2;
                    __half2 hv = __floats2half2_rn(acc[mt][nt][hh * 2 + 0],
                                                   acc[mt][nt][hh * 2 + 1]);
                    *(__half2*)(dst + (size_t)m * D + n) = hv;
                }
            }
        }
    }
}

// ---------------- CSR build (split kernels, run on s2 under gemm) ------------
__global__ void k_hist(const int* __restrict__ ei) {
    int t = blockIdx.x * blockDim.x + threadIdx.x;
    if (t >= N_EDGES / 2) return;
    if (g_is64) {
        longlong2 v = __ldg((const longlong2*)((const long long*)ei + N_EDGES) + t);
        atomicAdd(&g_cnt[(int)v.x], 1);
        atomicAdd(&g_cnt[(int)v.y], 1);
    } else {
        int2 v = __ldg((const int2*)(ei + N_EDGES) + t);
        atomicAdd(&g_cnt[v.x], 1);
        atomicAdd(&g_cnt[v.y], 1);
    }
}

__global__ void k_scan1() {
    __shared__ int sh[SCAN_BLK];
    int tid = threadIdx.x;
    int i = blockIdx.x * SCAN_BLK + tid;
    int v = (i < N_NODES) ? g_cnt[i] : 0;
    sh[tid] = v;
    __syncthreads();
    #pragma unroll
    for (int off = 1; off < SCAN_BLK; off <<= 1) {
        int t = (tid >= off) ? sh[tid - off] : 0;
        __syncthreads();
        sh[tid] += t;
        __syncthreads();
    }
    if (i < N_NODES) g_rowtmp[i] = sh[tid] - v;
    if (tid == SCAN_BLK - 1) g_partial[blockIdx.x] = sh[tid];
}

// merged scan2+scan3: each block prefix-sums the 98 partials locally
__global__ void k_scan23() {
    __shared__ int part[N_SCAN_BLKS];
    int tid = threadIdx.x;
    if (tid < N_SCAN_BLKS) part[tid] = g_partial[tid];
    __syncthreads();
    int i = blockIdx.x * blockDim.x + tid;
    if (i < N_NODES) {
        int chunk = i / SCAN_BLK;
        int pre = 0;
        for (int j = 0; j < chunk; j++) pre += part[j];
        int v = g_rowtmp[i] + pre;
        g_rowstart[i] = v;
        g_cur[i] = v;
    }
    if (i == 0) g_rowstart[N_NODES] = N_EDGES;
}

__global__ void k_scatter(const int* __restrict__ ei) {
    int t = blockIdx.x * blockDim.x + threadIdx.x;
    if (t >= N_EDGES / 2) return;
    int s0, d0, s1, d1;
    if (g_is64) {
        const long long* E = (const long long*)ei;
        longlong2 sv = __ldg((const longlong2*)E + t);
        longlong2 dv = __ldg((const longlong2*)(E + N_EDGES) + t);
        s0 = (int)sv.x; s1 = (int)sv.y; d0 = (int)dv.x; d1 = (int)dv.y;
    } else {
        int2 sv = __ldg((const int2*)ei + t);
        int2 dv = __ldg((const int2*)(ei + N_EDGES) + t);
        s0 = sv.x; s1 = sv.y; d0 = dv.x; d1 = dv.y;
    }
    g_csr[atomicAdd(&g_cur[d0], 1)] = s0;
    g_csr[atomicAdd(&g_cur[d1], 1)] = s1;
}

// ------ fused: mean-agg(y) + z + b1 -> hpre (fp16); one node per warp --------
__global__ void __launch_bounds__(256) k_aggfuse(const float* __restrict__ b1) {
    int gi = blockIdx.x * blockDim.x + threadIdx.x;
    int n = gi >> 5;
    int l = gi & 31;
    if (n >= N_NODES) return;
    int beg = g_rowstart[n], end = g_rowstart[n + 1];
    float4 a0 = make_float4(0.f, 0.f, 0.f, 0.f);
    float4 a1 = make_float4(0.f, 0.f, 0.f, 0.f);
    for (int base = beg; base < end; base += 32) {
        int cnt = min(32, end - base);
        int sid = (base + l < end) ? __ldg(g_csr + base + l) : 0;
        int j = 0;
        for (; j + 1 < cnt; j += 2) {
            int s0 = __shfl_sync(0xffffffffu, sid, j);
            int s1 = __shfl_sync(0xffffffffu, sid, j + 1);
            uint2 v0 = __ldg((const uint2*)(g_y + (size_t)s0 * D) + l);
            uint2 v1 = __ldg((const uint2*)(g_y + (size_t)s1 * D) + l);
            float2 p = __half22float2(*(__half2*)&v0.x);
            float2 r = __half22float2(*(__half2*)&v0.y);
            a0.x += p.x; a0.y += p.y; a0.z += r.x; a0.w += r.y;
            p = __half22float2(*(__half2*)&v1.x);
            r = __half22float2(*(__half2*)&v1.y);
            a1.x += p.x; a1.y += p.y; a1.z += r.x; a1.w += r.y;
        }
        if (j < cnt) {
            int s0 = __shfl_sync(0xffffffffu, sid, j);
            uint2 v0 = __ldg((const uint2*)(g_y + (size_t)s0 * D) + l);
            float2 p = __half22float2(*(__half2*)&v0.x);
            float2 r = __half22float2(*(__half2*)&v0.y);
            a0.x += p.x; a0.y += p.y; a0.z += r.x; a0.w += r.y;
        }
    }
    float inv = 1.0f / fmaxf((float)(end - beg), 1.0f);
    float4 bb = __ldg((const float4*)b1 + l);
    uint2 zv = __ldg((const uint2*)(g_z + (size_t)n * D) + l);
    float2 z0 = __half22float2(*(__half2*)&zv.x);
    float2 z1 = __half22float2(*(__half2*)&zv.y);
    float v0 = fmaf(a0.x + a1.x, inv, z0.x + bb.x);
    float v1 = fmaf(a0.y + a1.y, inv, z0.y + bb.y);
    float v2 = fmaf(a0.z + a1.z, inv, z1.x + bb.z);
    float v3 = fmaf(a0.w + a1.w, inv, z1.y + bb.w);
    __half2 h0 = __floats2half2_rn(v0, v1);
    __half2 h1 = __floats2half2_rn(v2, v3);
    *(uint2*)(g_hpre + (size_t)n * D + l * 4) =
        make_uint2(*(uint32_t*)&h0, *(uint32_t*)&h1);
    if (l == 0) g_inv[n] = inv;
}

// ---- fused BN1 stats + param fold + proj (grid barrier, 1480 blocks) --------
__global__ void __launch_bounds__(128) k_statsproj(
    const float* __restrict__ gamma1, const float* __restrict__ beta1,
    const float* __restrict__ W2l, const float* __restrict__ W2r) {
    __shared__ float s_scale[128], s_shift[128];
    const int c = threadIdx.x;           // 128 threads: one column each

    // phase 1: BN1 column stats over hpre
    float s = 0.f, q = 0.f;
    for (int r = blockIdx.x; r < N_NODES; r += NB_SP) {
        float v = __half2float(g_hpre[(size_t)r * D + c]);
        s += v; q += v * v;
    }
    atomicAdd(&g_s1[c], (double)s);
    atomicAdd(&g_q1[c], (double)q);

    grid_bar(&g_bc1, &g_bp1, NB_SP, 1);

    // phase 2: fold params locally (L1 fresh: no prior reads of g_s1 this launch)
    {
        double mu  = g_s1[c] / (double)N_NODES;
        double var = g_q1[c] / (double)N_NODES - mu * mu;
        double sc  = (double)gamma1[c] / sqrt(var + (double)BN_EPS);
        s_scale[c] = (float)sc;
        s_shift[c] = (float)((double)beta1[c] - mu * sc);
    }
    __syncthreads();

    // phase 3: proj — warp per node, grid-stride
    const int w = c >> 5, lane = c & 31;
    for (int n = blockIdx.x * 4 + w; n < N_NODES; n += NB_SP * 4) {
        uint2 hv2 = __ldg((const uint2*)(g_hpre + (size_t)n * D) + lane);
        float2 fa = __half22float2(*(__half2*)&hv2.x);
        float2 fb = __half22float2(*(__half2*)&hv2.y);
        float hv[4] = {fa.x, fa.y, fb.x, fb.y};
        float p0 = 0.f, p1 = 0.f, r0 = 0.f, r1 = 0.f;
        #pragma unroll
        for (int j = 0; j < 4; j++) {
            int cc = lane * 4 + j;
            float v = fmaxf(fmaf(hv[j], s_scale[cc], s_shift[cc]), 0.f);
            p0 = fmaf(v, __ldg(W2l + 2 * cc),     p0);
            p1 = fmaf(v, __ldg(W2l + 2 * cc + 1), p1);
            r0 = fmaf(v, __ldg(W2r + 2 * cc),     r0);
            r1 = fmaf(v, __ldg(W2r + 2 * cc + 1), r1);
        }
        #pragma unroll
        for (int o = 16; o; o >>= 1) {
            p0 += __shfl_xor_sync(0xffffffffu, p0, o);
            p1 += __shfl_xor_sync(0xffffffffu, p1, o);
            r0 += __shfl_xor_sync(0xffffffffu, r0, o);
            r1 += __shfl_xor_sync(0xffffffffu, r1, o);
        }
        if (lane == 0) {
            *(float2*)(g_p + 2 * n) = make_float2(p0, p1);
            *(float2*)(g_r + 2 * n) = make_float2(r0, r1);
        }
    }
}

// ---- fused layer-2 gather + BN2 stats + log_softmax (grid barrier) ----------
__global__ void __launch_bounds__(256) k_l2final(
    const float* __restrict__ b2, const float* __restrict__ gamma2,
    const float* __restrict__ beta2, float* __restrict__ out) {
    int i = blockIdx.x * blockDim.x + threadIdx.x;
    float o0 = 0.f, o1 = 0.f;
    if (i < N_NODES) {
        int beg = g_rowstart[i], end = g_rowstart[i + 1];
        float s0 = 0.f, s1 = 0.f, t0 = 0.f, t1 = 0.f;
        int e = beg;
        for (; e + 1 < end; e += 2) {
            int sa = __ldg(g_csr + e);
            int sb = __ldg(g_csr + e + 1);
            float2 va = *(const float2*)(g_p + 2 * sa);
            float2 vb = *(const float2*)(g_p + 2 * sb);
            s0 += va.x; s1 += va.y;
            t0 += vb.x; t1 += vb.y;
        }
        if (e < end) {
            int sa = __ldg(g_csr + e);
            float2 va = *(const float2*)(g_p + 2 * sa);
            s0 += va.x; s1 += va.y;
        }
        s0 += t0; s1 += t1;
        float inv = g_inv[i];
        float2 r = *(const float2*)(g_r + 2 * i);
        o0 = fmaf(s0, inv, __ldg(b2) + r.x);
        o1 = fmaf(s1, inv, __ldg(b2 + 1) + r.y);
    }
    // block-reduce BN2 stats
    float q0 = o0 * o0, q1 = o1 * o1;
    float a0 = o0, a1 = o1;
    #pragma unroll
    for (int o = 16; o; o >>= 1) {
        a0 += __shfl_xor_sync(0xffffffffu, a0, o);
        a1 += __shfl_xor_sync(0xffffffffu, a1, o);
        q0 += __shfl_xor_sync(0xffffffffu, q0, o);
        q1 += __shfl_xor_sync(0xffffffffu, q1, o);
    }
    __shared__ float sh[4][8];
    int w = threadIdx.x >> 5, ll = threadIdx.x & 31;
    if (ll == 0) { sh[0][w] = a0; sh[1][w] = a1; sh[2][w] = q0; sh[3][w] = q1; }
    __syncthreads();
    if (threadIdx.x == 0) {
        float s0 = 0.f, s1 = 0.f, t0 = 0.f, t1 = 0.f;
        #pragma unroll
        for (int k = 0; k < 8; k++) { s0 += sh[0][k]; s1 += sh[1][k]; t0 += sh[2][k]; t1 += sh[3][k]; }
        atomicAdd(&g_s2[0], (double)s0);
        atomicAdd(&g_s2[1], (double)s1);
        atomicAdd(&g_q2[0], (double)t0);
        atomicAdd(&g_q2[1], (double)t1);
    }

    grid_bar(&g_bc2, &g_bp2, NB_L2, 1);

    // phase 2: BN2 + log_softmax from registers (opre never hits memory)
    if (i < N_NODES) {
        double mu0 = g_s2[0] / (double)N_NODES;
        double mu1 = g_s2[1] / (double)N_NODES;
        double v0  = g_q2[0] / (double)N_NODES - mu0 * mu0;
        double v1  = g_q2[1] / (double)N_NODES - mu1 * mu1;
        float sc0 = (float)((double)__ldg(gamma2)     / sqrt(v0 + (double)BN_EPS));
        float sc1 = (float)((double)__ldg(gamma2 + 1) / sqrt(v1 + (double)BN_EPS));
        float sh0 = (float)((double)__ldg(beta2)     - mu0 * sc0);
        float sh1 = (float)((double)__ldg(beta2 + 1) - mu1 * sc1);
        float a = fmaf(o0, sc0, sh0);
        float b = fmaf(o1, sc1, sh1);
        float m = fmaxf(a, b);
        float lse = m + logf(expf(a - m) + expf(b - m));
        *(float2*)(out + 2 * i) = make_float2(a - lse, b - lse);
    }
}

// ---------------- launch: CSR chain (s2) overlaps gemm (main) ----------------
extern "C" void kernel_launch(void* const* d_in, const int* in_sizes, int n_in,
                              void* d_out, int out_size) {
    const float* x    = (const float*)d_in[0];
    const int*   ei   = (const int*)d_in[1];
    const float* W1l  = (const float*)d_in[2];
    const float* b1   = (const float*)d_in[3];
    const float* W1r  = (const float*)d_in[4];
    const float* g1   = (const float*)d_in[5];
    const float* be1  = (const float*)d_in[6];
    const float* W2l  = (const float*)d_in[7];
    const float* b2   = (const float*)d_in[8];
    const float* W2r  = (const float*)d_in[9];
    const float* g2   = (const float*)d_in[10];
    const float* be2  = (const float*)d_in[11];
    float* out = (float*)d_out;

    cudaStream_t s2;
    cudaStreamCreateWithFlags(&s2, cudaStreamNonBlocking);
    cudaEvent_t e1, e2;
    cudaEventCreateWithFlags(&e1, cudaEventDisableTiming);
    cudaEventCreateWithFlags(&e2, cudaEventDisableTiming);

    k_prep<<<200, 256>>>(ei, W1l, W1r);                          // 1
    cudaEventRecord(e1, 0);
    cudaStreamWaitEvent(s2, e1, 0);                              // fork

    k_hist<<<(N_EDGES / 2 + 255) / 256, 256, 0, s2>>>(ei);       // 2 (s2)
    k_scan1<<<N_SCAN_BLKS, SCAN_BLK, 0, s2>>>();                 // 3 (s2)
    k_gemm1<<<dim3((N_NODES + 127) / 128, 2), 256>>>(x);         // 4 (main)
    k_scan23<<<(N_NODES + 255) / 256, 256, 0, s2>>>();           // 5 (s2)
    k_scatter<<<(N_EDGES / 2 + 255) / 256, 256, 0, s2>>>(ei);    // 6 (s2)

    cudaEventRecord(e2, s2);
    cudaStreamWaitEvent(0, e2, 0);                               // join

    k_aggfuse<<<(N_NODES * 32 + 255) / 256, 256>>>(b1);          // 7
    k_statsproj<<<NB_SP, 128>>>(g1, be1, W2l, W2r);              // 8
    k_l2final<<<NB_L2, 256>>>(b2, g2, be2, out);                 // 9
}

// round 14
// speedup vs baseline: 1.2998x; 1.0285x over previous
#include <cuda_runtime.h>
#include <cuda_bf16.h>
#include <cuda_fp16.h>
#include <math.h>
#include <stdint.h>

#define N_NODES 100000
#define N_EDGES 1600000
#define D 128
#define BN_EPS 1e-5f
#define SCAN_BLK 1024
#define N_SCAN_BLKS ((N_NODES + SCAN_BLK - 1) / SCAN_BLK)   // 98
#define NB_SP 1480
#define NB_L2 ((N_NODES + 255) / 256)   // 391

// ---------------- scratch (allocation-free: __device__ globals) ----------------
__device__ __align__(16) __nv_bfloat16 g_xh[(size_t)N_NODES * D];  // x hi split
__device__ __align__(16) __nv_bfloat16 g_xl[(size_t)N_NODES * D];  // x lo split
__device__ __align__(16) __half g_y[(size_t)N_NODES * D];     // x @ W1l (fp16)
__device__ __align__(16) __half g_z[(size_t)N_NODES * D];     // x @ W1r (fp16)
__device__ __align__(16) __half g_hpre[(size_t)N_NODES * D];  // pre-BN h1 (fp16)
__device__ float  g_inv [N_NODES];
__device__ float  g_p   [N_NODES * 2];
__device__ float  g_r   [N_NODES * 2];
__device__ double g_s1[D], g_q1[D];
__device__ double g_s2[2], g_q2[2];
__device__ int    g_is64;
__device__ int    g_bc1, g_bp1;
__device__ int    g_bc2, g_bp2;
// transposed + bf16-split weights: [n=256][k=128]
__device__ __align__(16) __nv_bfloat16 g_wt_h[256 * 128];
__device__ __align__(16) __nv_bfloat16 g_wt_l[256 * 128];
// CSR build
__device__ int    g_cnt[N_NODES];
__device__ int    g_rowtmp[N_NODES];
__device__ int    g_rowstart[N_NODES + 1];
__device__ int    g_cur[N_NODES];
__device__ int    g_partial[N_SCAN_BLKS];
__device__ int    g_csr[N_EDGES];

// ---------------- helpers ----------------
__device__ __forceinline__ uint32_t smem_u32(const void* p) {
    uint32_t a;
    asm("{ .reg .u64 t; cvta.to.shared.u64 t, %1; cvt.u32.u64 %0, t; }" : "=r"(a) : "l"(p));
    return a;
}
__device__ __forceinline__ void bf16_split2(float x0, float x1, uint32_t& hi, uint32_t& lo) {
    __nv_bfloat16 h0 = __float2bfloat16(x0), h1 = __float2bfloat16(x1);
    __nv_bfloat162 hp = __halves2bfloat162(h0, h1);
    __nv_bfloat162 lp = __halves2bfloat162(
        __float2bfloat16(x0 - __bfloat162float(h0)),
        __float2bfloat16(x1 - __bfloat162float(h1)));
    hi = *(uint32_t*)&hp;
    lo = *(uint32_t*)&lp;
}
#define LDSM4(r, addr) \
    asm volatile("ldmatrix.sync.aligned.m8n8.x4.shared.b16 {%0,%1,%2,%3}, [%4];" \
        : "=r"((r)[0]), "=r"((r)[1]), "=r"((r)[2]), "=r"((r)[3]) : "r"(addr))
#define MMA16816(c, a, b0, b1) \
    asm volatile("mma.sync.aligned.m16n8k16.row.col.f32.bf16.bf16.f32 " \
        "{%0,%1,%2,%3}, {%4,%5,%6,%7}, {%8,%9}, {%0,%1,%2,%3};" \
        : "+f"((c)[0]), "+f"((c)[1]), "+f"((c)[2]), "+f"((c)[3]) \
        : "r"((a)[0]), "r"((a)[1]), "r"((a)[2]), "r"((a)[3]), "r"(b0), "r"(b1))
#define CP_ASYNC16(dst, src) \
    asm volatile("cp.async.cg.shared.global [%0], [%1], 16;" :: "r"(dst), "l"(src) : "memory")
#define CP_COMMIT()  asm volatile("cp.async.commit_group;" ::: "memory")
#define CP_WAIT1()   asm volatile("cp.async.wait_group 1;" ::: "memory")
#define CP_WAIT0()   asm volatile("cp.async.wait_group 0;" ::: "memory")

// grid barrier for co-resident grids (kernel runs alone on the GPU)
__device__ __forceinline__ void grid_bar(int* cnt, int* phs, int nblk, int phase) {
    __syncthreads();
    if (threadIdx.x == 0) {
        __threadfence();
        int t = atomicAdd(cnt, 1);
        if (t == nblk * phase - 1) {
            atomicExch(phs, phase);
        } else {
            while (atomicAdd(phs, 0) < phase) __nanosleep(64);
        }
        __threadfence();
    }
    __syncthreads();
}

// ---------------- prep: dtype detect + zero scratch + W split ----------------
__global__ void k_prep(const int* __restrict__ ei,
                       const float* __restrict__ W1l, const float* __restrict__ W1r) {
    int i = blockIdx.x * blockDim.x + threadIdx.x;
    int stride = gridDim.x * blockDim.x;
    if (blockIdx.x == 0) {
        __shared__ int any_nonzero;
        if (threadIdx.x == 0) any_nonzero = 0;
        __syncthreads();
        int v = ei[2 * threadIdx.x + 1];
        if (v != 0) atomicOr(&any_nonzero, 1);
        __syncthreads();
        if (threadIdx.x == 0) {
            g_is64 = (any_nonzero == 0) ? 1 : 0;
            g_bc1 = 0; g_bp1 = 0; g_bc2 = 0; g_bp2 = 0;
        }
    }
    for (int j = i; j < N_NODES; j += stride) g_cnt[j] = 0;
    if (i < D) { g_s1[i] = 0.0; g_q1[i] = 0.0; }
    if (i < 2) { g_s2[i] = 0.0; g_q2[i] = 0.0; }
    for (int j = i; j < 256 * 128; j += stride) {
        int n = j >> 7, k = j & 127;
        float w = (n < 128) ? __ldg(W1l + k * 128 + n) : __ldg(W1r + k * 128 + (n - 128));
        __nv_bfloat16 h = __float2bfloat16(w);
        g_wt_h[j] = h;
        g_wt_l[j] = __float2bfloat16(w - __bfloat162float(h));
    }
}

// ---------------- x -> bf16 hi/lo split (overlaps CSR chain) ------------------
__global__ void k_xconv(const float* __restrict__ x) {
    int i = blockIdx.x * blockDim.x + threadIdx.x;
    int stride = gridDim.x * blockDim.x;
    for (int j = i; j < N_NODES * D / 4; j += stride) {
        float4 v = __ldg((const float4*)x + j);
        uint32_t h0, l0, h1, l1;
        bf16_split2(v.x, v.y, h0, l0);
        bf16_split2(v.z, v.w, h1, l1);
        ((uint2*)g_xh)[j] = make_uint2(h0, h1);
        ((uint2*)g_xl)[j] = make_uint2(l0, l1);
    }
}

// ---------------- layer-1 GEMM: [y|z] = x @ [W1l|W1r], cp.async pipeline ------
#define LDA 40                 // smem row stride in bf16 (32 + 8 pad)
#define TS_B 10240             // one tile: 128 * LDA * 2 bytes
#define STAGE_B (4 * TS_B)     // Ah, Al, Bh, Bl
#define GSM_TOT (2 * STAGE_B)  // 81920 bytes

__global__ void __launch_bounds__(256, 2) k_gemm1() {
    extern __shared__ __align__(16) char dsm[];
    const int tid = threadIdx.x;
    const int wid = tid >> 5, l = tid & 31;
    const int warp_m = wid >> 2, warp_n = wid & 3;
    const int m0 = blockIdx.x * 128;
    const int nh = blockIdx.y;
    const uint32_t sbase = smem_u32(dsm);

    float acc[4][4][4];
    #pragma unroll
    for (int i = 0; i < 4; i++)
        #pragma unroll
        for (int j = 0; j < 4; j++)
            #pragma unroll
            for (int c = 0; c < 4; c++) acc[i][j][c] = 0.f;

    // stage one BK=32 tile set (Ah/Al/Bh/Bl) via cp.async; 8 chunks/thread
    auto issueT = [&](int kc, int st) {
        char* base = dsm + st * STAGE_B;
        #pragma unroll
        for (int i = 0; i < 2; i++) {
            int c   = tid + i * 256;          // 0..511
            int row = c >> 2, seg = c & 3;
            uint32_t doff = (uint32_t)((row * LDA + seg * 8) * 2);
            uint32_t dAh = smem_u32(base) + doff;
            int m = m0 + row;
            if (m < N_NODES) {
                CP_ASYNC16(dAh,            (const char*)(g_xh + (size_t)m * D + kc + seg * 8));
                CP_ASYNC16(dAh + TS_B,     (const char*)(g_xl + (size_t)m * D + kc + seg * 8));
            } else {
                *(uint4*)(base + doff)        = make_uint4(0, 0, 0, 0);
                *(uint4*)(base + TS_B + doff) = make_uint4(0, 0, 0, 0);
            }
            const size_t wo = (size_t)(nh * 128 + row) * D + kc + seg * 8;
            CP_ASYNC16(dAh + 2 * TS_B, (const char*)(g_wt_h + wo));
            CP_ASYNC16(dAh + 3 * TS_B, (const char*)(g_wt_l + wo));
        }
        CP_COMMIT();
    };

    issueT(0, 0);
    issueT(32, 1);

    for (int kt = 0; kt < 4; kt++) {
        if (kt < 3) CP_WAIT1(); else CP_WAIT0();
        __syncthreads();
        const uint32_t sAh = sbase + (kt & 1) * STAGE_B;
        const uint32_t sAl = sAh + TS_B;
        const uint32_t sBh = sAh + 2 * TS_B;
        const uint32_t sBl = sAh + 3 * TS_B;
        #pragma unroll
        for (int kk = 0; kk < 2; kk++) {
            uint32_t ah[4][4], al[4][4], bhf[2][4], blf[2][4];
            #pragma unroll
            for (int mt = 0; mt < 4; mt++) {
                uint32_t off = (uint32_t)(((warp_m * 64 + mt * 16 + (l & 15)) * LDA
                                           + kk * 16 + (l >> 4) * 8) * 2);
                LDSM4(ah[mt], sAh + off);
                LDSM4(al[mt], sAl + off);
            }
            #pragma unroll
            for (int p = 0; p < 2; p++) {
                uint32_t off = (uint32_t)(((warp_n * 32 + p * 16 + (l >> 4) * 8 + (l & 7)) * LDA
                                           + kk * 16 + ((l >> 3) & 1) * 8) * 2);
                LDSM4(bhf[p], sBh + off);
                LDSM4(blf[p], sBl + off);
            }
            #pragma unroll
            for (int mt = 0; mt < 4; mt++)
                #pragma unroll
                for (int nt = 0; nt < 4; nt++) {
                    const int p = nt >> 1, q = nt & 1;
                    MMA16816(acc[mt][nt], ah[mt], bhf[p][2 * q], bhf[p][2 * q + 1]);
                    MMA16816(acc[mt][nt], ah[mt], blf[p][2 * q], blf[p][2 * q + 1]);
                    MMA16816(acc[mt][nt], al[mt], bhf[p][2 * q], bhf[p][2 * q + 1]);
                }
        }
        __syncthreads();
        if (kt + 2 < 4) issueT((kt + 2) * 32, kt & 1);
    }

    // ---- epilogue: store fp16 y/z ----
    __half* dst = nh ? g_z : g_y;
    #pragma unroll
    for (int mt = 0; mt < 4; mt++) {
        #pragma unroll
        for (int hh = 0; hh < 2; hh++) {
            int m = m0 + warp_m * 64 + mt * 16 + hh * 8 + (l >> 2);
            if (m < N_NODES) {
                #pragma unroll
                for (int nt = 0; nt < 4; nt++) {
                    int n = warp_n * 32 + nt * 8 + (l & 3) * 2;
                    __half2 hv = __floats2half2_rn(acc[mt][nt][hh * 2 + 0],
                                                   acc[mt][nt][hh * 2 + 1]);
                    *(__half2*)(dst + (size_t)m * D + n) = hv;
                }
            }
        }
    }
}

// ---------------- CSR build (split kernels, run on s2 under gemm) ------------
__global__ void k_hist(const int* __restrict__ ei) {
    int t = blockIdx.x * blockDim.x + threadIdx.x;
    if (t >= N_EDGES / 2) return;
    if (g_is64) {
        longlong2 v = __ldg((const longlong2*)((const long long*)ei + N_EDGES) + t);
        atomicAdd(&g_cnt[(int)v.x], 1);
        atomicAdd(&g_cnt[(int)v.y], 1);
    } else {
        int2 v = __ldg((const int2*)(ei + N_EDGES) + t);
        atomicAdd(&g_cnt[v.x], 1);
        atomicAdd(&g_cnt[v.y], 1);
    }
}

__global__ void k_scan1() {
    __shared__ int sh[SCAN_BLK];
    int tid = threadIdx.x;
    int i = blockIdx.x * SCAN_BLK + tid;
    int v = (i < N_NODES) ? g_cnt[i] : 0;
    sh[tid] = v;
    __syncthreads();
    #pragma unroll
    for (int off = 1; off < SCAN_BLK; off <<= 1) {
        int t = (tid >= off) ? sh[tid - off] : 0;
        __syncthreads();
        sh[tid] += t;
        __syncthreads();
    }
    if (i < N_NODES) g_rowtmp[i] = sh[tid] - v;
    if (tid == SCAN_BLK - 1) g_partial[blockIdx.x] = sh[tid];
}

__global__ void k_scan23() {
    __shared__ int part[N_SCAN_BLKS];
    int tid = threadIdx.x;
    if (tid < N_SCAN_BLKS) part[tid] = g_partial[tid];
    __syncthreads();
    int i = blockIdx.x * blockDim.x + tid;
    if (i < N_NODES) {
        int chunk = i / SCAN_BLK;
        int pre = 0;
        for (int j = 0; j < chunk; j++) pre += part[j];
        int v = g_rowtmp[i] + pre;
        g_rowstart[i] = v;
        g_cur[i] = v;
    }
    if (i == 0) g_rowstart[N_NODES] = N_EDGES;
}

__global__ void k_scatter(const int* __restrict__ ei) {
    int t = blockIdx.x * blockDim.x + threadIdx.x;
    if (t >= N_EDGES / 2) return;
    int s0, d0, s1, d1;
    if (g_is64) {
        const long long* E = (const long long*)ei;
        longlong2 sv = __ldg((const longlong2*)E + t);
        longlong2 dv = __ldg((const longlong2*)(E + N_EDGES) + t);
        s0 = (int)sv.x; s1 = (int)sv.y; d0 = (int)dv.x; d1 = (int)dv.y;
    } else {
        int2 sv = __ldg((const int2*)ei + t);
        int2 dv = __ldg((const int2*)(ei + N_EDGES) + t);
        s0 = sv.x; s1 = sv.y; d0 = dv.x; d1 = dv.y;
    }
    g_csr[atomicAdd(&g_cur[d0], 1)] = s0;
    g_csr[atomicAdd(&g_cur[d1], 1)] = s1;
}

// ------ fused: mean-agg(y) + z + b1 -> hpre (fp16); one node per warp --------
__global__ void __launch_bounds__(256) k_aggfuse(const float* __restrict__ b1) {
    int gi = blockIdx.x * blockDim.x + threadIdx.x;
    int n = gi >> 5;
    int l = gi & 31;
    if (n >= N_NODES) return;
    int beg = g_rowstart[n], end = g_rowstart[n + 1];
    float4 a0 = make_float4(0.f, 0.f, 0.f, 0.f);
    float4 a1 = make_float4(0.f, 0.f, 0.f, 0.f);
    for (int base = beg; base < end; base += 32) {
        int cnt = min(32, end - base);
        int sid = (base + l < end) ? __ldg(g_csr + base + l) : 0;
        int j = 0;
        for (; j + 1 < cnt; j += 2) {
            int s0 = __shfl_sync(0xffffffffu, sid, j);
            int s1 = __shfl_sync(0xffffffffu, sid, j + 1);
            uint2 v0 = __ldg((const uint2*)(g_y + (size_t)s0 * D) + l);
            uint2 v1 = __ldg((const uint2*)(g_y + (size_t)s1 * D) + l);
            float2 p = __half22float2(*(__half2*)&v0.x);
            float2 r = __half22float2(*(__half2*)&v0.y);
            a0.x += p.x; a0.y += p.y; a0.z += r.x; a0.w += r.y;
            p = __half22float2(*(__half2*)&v1.x);
            r = __half22float2(*(__half2*)&v1.y);
            a1.x += p.x; a1.y += p.y; a1.z += r.x; a1.w += r.y;
        }
        if (j < cnt) {
            int s0 = __shfl_sync(0xffffffffu, sid, j);
            uint2 v0 = __ldg((const uint2*)(g_y + (size_t)s0 * D) + l);
            float2 p = __half22float2(*(__half2*)&v0.x);
            float2 r = __half22float2(*(__half2*)&v0.y);
            a0.x += p.x; a0.y += p.y; a0.z += r.x; a0.w += r.y;
        }
    }
    float inv = 1.0f / fmaxf((float)(end - beg), 1.0f);
    float4 bb = __ldg((const float4*)b1 + l);
    uint2 zv = __ldg((const uint2*)(g_z + (size_t)n * D) + l);
    float2 z0 = __half22float2(*(__half2*)&zv.x);
    float2 z1 = __half22float2(*(__half2*)&zv.y);
    float v0 = fmaf(a0.x + a1.x, inv, z0.x + bb.x);
    float v1 = fmaf(a0.y + a1.y, inv, z0.y + bb.y);
    float v2 = fmaf(a0.z + a1.z, inv, z1.x + bb.z);
    float v3 = fmaf(a0.w + a1.w, inv, z1.y + bb.w);
    __half2 h0 = __floats2half2_rn(v0, v1);
    __half2 h1 = __floats2half2_rn(v2, v3);
    *(uint2*)(g_hpre + (size_t)n * D + l * 4) =
        make_uint2(*(uint32_t*)&h0, *(uint32_t*)&h1);
    if (l == 0) g_inv[n] = inv;
}

// ---- fused BN1 stats + param fold + proj (grid barrier, 1480 blocks) --------
__global__ void __launch_bounds__(128) k_statsproj(
    const float* __restrict__ gamma1, const float* __restrict__ beta1,
    const float* __restrict__ W2l, const float* __restrict__ W2r) {
    __shared__ float s_scale[128], s_shift[128];
    const int c = threadIdx.x;

    float s = 0.f, q = 0.f;
    for (int r = blockIdx.x; r < N_NODES; r += NB_SP) {
        float v = __half2float(g_hpre[(size_t)r * D + c]);
        s += v; q += v * v;
    }
    atomicAdd(&g_s1[c], (double)s);
    atomicAdd(&g_q1[c], (double)q);

    grid_bar(&g_bc1, &g_bp1, NB_SP, 1);

    {
        double mu  = g_s1[c] / (double)N_NODES;
        double var = g_q1[c] / (double)N_NODES - mu * mu;
        double sc  = (double)gamma1[c] / sqrt(var + (double)BN_EPS);
        s_scale[c] = (float)sc;
        s_shift[c] = (float)((double)beta1[c] - mu * sc);
    }
    __syncthreads();

    const int w = c >> 5, lane = c & 31;
    for (int n = blockIdx.x * 4 + w; n < N_NODES; n += NB_SP * 4) {
        uint2 hv2 = __ldg((const uint2*)(g_hpre + (size_t)n * D) + lane);
        float2 fa = __half22float2(*(__half2*)&hv2.x);
        float2 fb = __half22float2(*(__half2*)&hv2.y);
        float hv[4] = {fa.x, fa.y, fb.x, fb.y};
        float p0 = 0.f, p1 = 0.f, r0 = 0.f, r1 = 0.f;
        #pragma unroll
        for (int j = 0; j < 4; j++) {
            int cc = lane * 4 + j;
            float v = fmaxf(fmaf(hv[j], s_scale[cc], s_shift[cc]), 0.f);
            p0 = fmaf(v, __ldg(W2l + 2 * cc),     p0);
            p1 = fmaf(v, __ldg(W2l + 2 * cc + 1), p1);
            r0 = fmaf(v, __ldg(W2r + 2 * cc),     r0);
            r1 = fmaf(v, __ldg(W2r + 2 * cc + 1), r1);
        }
        #pragma unroll
        for (int o = 16; o; o >>= 1) {
            p0 += __shfl_xor_sync(0xffffffffu, p0, o);
            p1 += __shfl_xor_sync(0xffffffffu, p1, o);
            r0 += __shfl_xor_sync(0xffffffffu, r0, o);
            r1 += __shfl_xor_sync(0xffffffffu, r1, o);
        }
        if (lane == 0) {
            *(float2*)(g_p + 2 * n) = make_float2(p0, p1);
            *(float2*)(g_r + 2 * n) = make_float2(r0, r1);
        }
    }
}

// ---- fused layer-2 gather + BN2 stats + log_softmax (grid barrier) ----------
__global__ void __launch_bounds__(256) k_l2final(
    const float* __restrict__ b2, const float* __restrict__ gamma2,
    const float* __restrict__ beta2, float* __restrict__ out) {
    int i = blockIdx.x * blockDim.x + threadIdx.x;
    float o0 = 0.f, o1 = 0.f;
    if (i < N_NODES) {
        int beg = g_rowstart[i], end = g_rowstart[i + 1];
        float s0 = 0.f, s1 = 0.f, t0 = 0.f, t1 = 0.f;
        int e = beg;
        for (; e + 1 < end; e += 2) {
            int sa = __ldg(g_csr + e);
            int sb = __ldg(g_csr + e + 1);
            float2 va = *(const float2*)(g_p + 2 * sa);
            float2 vb = *(const float2*)(g_p + 2 * sb);
            s0 += va.x; s1 += va.y;
            t0 += vb.x; t1 += vb.y;
        }
        if (e < end) {
            int sa = __ldg(g_csr + e);
            float2 va = *(const float2*)(g_p + 2 * sa);
            s0 += va.x; s1 += va.y;
        }
        s0 += t0; s1 += t1;
        float inv = g_inv[i];
        float2 r = *(const float2*)(g_r + 2 * i);
        o0 = fmaf(s0, inv, __ldg(b2) + r.x);
        o1 = fmaf(s1, inv, __ldg(b2 + 1) + r.y);
    }
    float q0 = o0 * o0, q1 = o1 * o1;
    float a0 = o0, a1 = o1;
    #pragma unroll
    for (int o = 16; o; o >>= 1) {
        a0 += __shfl_xor_sync(0xffffffffu, a0, o);
        a1 += __shfl_xor_sync(0xffffffffu, a1, o);
        q0 += __shfl_xor_sync(0xffffffffu, q0, o);
        q1 += __shfl_xor_sync(0xffffffffu, q1, o);
    }
    __shared__ float sh[4][8];
    int w = threadIdx.x >> 5, ll = threadIdx.x & 31;
    if (ll == 0) { sh[0][w] = a0; sh[1][w] = a1; sh[2][w] = q0; sh[3][w] = q1; }
    __syncthreads();
    if (threadIdx.x == 0) {
        float s0 = 0.f, s1 = 0.f, t0 = 0.f, t1 = 0.f;
        #pragma unroll
        for (int k = 0; k < 8; k++) { s0 += sh[0][k]; s1 += sh[1][k]; t0 += sh[2][k]; t1 += sh[3][k]; }
        atomicAdd(&g_s2[0], (double)s0);
        atomicAdd(&g_s2[1], (double)s1);
        atomicAdd(&g_q2[0], (double)t0);
        atomicAdd(&g_q2[1], (double)t1);
    }

    grid_bar(&g_bc2, &g_bp2, NB_L2, 1);

    if (i < N_NODES) {
        double mu0 = g_s2[0] / (double)N_NODES;
        double mu1 = g_s2[1] / (double)N_NODES;
        double v0  = g_q2[0] / (double)N_NODES - mu0 * mu0;
        double v1  = g_q2[1] / (double)N_NODES - mu1 * mu1;
        float sc0 = (float)((double)__ldg(gamma2)     / sqrt(v0 + (double)BN_EPS));
        float sc1 = (float)((double)__ldg(gamma2 + 1) / sqrt(v1 + (double)BN_EPS));
        float sh0 = (float)((double)__ldg(beta2)     - mu0 * sc0);
        float sh1 = (float)((double)__ldg(beta2 + 1) - mu1 * sc1);
        float a = fmaf(o0, sc0, sh0);
        float b = fmaf(o1, sc1, sh1);
        float m = fmaxf(a, b);
        float lse = m + logf(expf(a - m) + expf(b - m));
        *(float2*)(out + 2 * i) = make_float2(a - lse, b - lse);
    }
}

// ---------------- launch ----------------
extern "C" void kernel_launch(void* const* d_in, const int* in_sizes, int n_in,
                              void* d_out, int out_size) {
    const float* x    = (const float*)d_in[0];
    const int*   ei   = (const int*)d_in[1];
    const float* W1l  = (const float*)d_in[2];
    const float* b1   = (const float*)d_in[3];
    const float* W1r  = (const float*)d_in[4];
    const float* g1   = (const float*)d_in[5];
    const float* be1  = (const float*)d_in[6];
    const float* W2l  = (const float*)d_in[7];
    const float* b2   = (const float*)d_in[8];
    const float* W2r  = (const float*)d_in[9];
    const float* g2   = (const float*)d_in[10];
    const float* be2  = (const float*)d_in[11];
    float* out = (float*)d_out;

    cudaFuncSetAttribute(k_gemm1, cudaFuncAttributeMaxDynamicSharedMemorySize, GSM_TOT);

    cudaStream_t s2;
    cudaStreamCreateWithFlags(&s2, cudaStreamNonBlocking);
    cudaEvent_t e1, e2;
    cudaEventCreateWithFlags(&e1, cudaEventDisableTiming);
    cudaEventCreateWithFlags(&e2, cudaEventDisableTiming);

    k_prep<<<200, 256>>>(ei, W1l, W1r);                          // 1 (main)
    cudaEventRecord(e1, 0);
    cudaStreamWaitEvent(s2, e1, 0);                              // fork

    k_xconv<<<800, 256>>>(x);                                    // 2 (main)
    k_hist<<<(N_EDGES / 2 + 255) / 256, 256, 0, s2>>>(ei);       // 3 (s2)
    k_gemm1<<<dim3((N_NODES + 127) / 128, 2), 256, GSM_TOT>>>(); // 4 (main, profiled)
    k_scan1<<<N_SCAN_BLKS, SCAN_BLK, 0, s2>>>();                 // 5 (s2)
    k_scan23<<<(N_NODES + 255) / 256, 256, 0, s2>>>();           // 6 (s2)
    k_scatter<<<(N_EDGES / 2 + 255) / 256, 256, 0, s2>>>(ei);    // 7 (s2)

    cudaEventRecord(e2, s2);
    cudaStreamWaitEvent(0, e2, 0);                               // join

    k_aggfuse<<<(N_NODES * 32 + 255) / 256, 256>>>(b1);          // 8
    k_statsproj<<<NB_SP, 128>>>(g1, be1, W2l, W2r);              // 9
    k_l2final<<<NB_L2, 256>>>(b2, g2, be2, out);                 // 10
}